// round 3
// baseline (speedup 1.0000x reference)
#include <cuda_runtime.h>
#include <math.h>

// ---------------- problem constants ----------------
#define B_    2
#define C_    128
#define T_    4
#define HH_   64
#define WW_   64
#define NH_   32        // heads == groupnorm groups
#define DH_   4         // head dim
#define SPAT  16384     // T*H*W
#define NTOK  1024      // T * (H/4) * (W/4)
#define PP_   16        // pixels per patch
#define TBL_  6727      // (2T-1)*(2h-1)*(2w-1)

// ---------------- scratch (device globals; no runtime alloc) ----------------
__device__ float g_y[3][B_][C_][SPAT];        // raw q/k/v projections (50 MB)
__device__ float g_part[3][B_][NH_][256][2];  // per-s-tile partial (sum, sumsq)
__device__ float g_stats[3][B_][NH_][2];      // (mean, rstd)
__device__ float g_qp[B_][NH_][NTOK][DH_];    // pooled queries  (float4/token)
__device__ float g_kp[B_][NH_][NTOK][DH_];    // pooled keys
__device__ float g_vp[B_][NH_][NTOK][DH_*PP_];// full-res values [m][d*16+p]

// ================= K1: 1x1x1 conv projections + GN partial stats ============
// grid: (256 s-tiles, B, 3 proj), block 256. Tile: 128 o x 64 s.
__global__ __launch_bounds__(256) void proj_kernel(
    const float* __restrict__ x,
    const float* __restrict__ Wq,
    const float* __restrict__ Wk,
    const float* __restrict__ Wv)
{
    __shared__ float Wt[128][132];   // W transposed [c][o], padded
    __shared__ float Xs[16][68];     // x chunk [c][s], padded

    const int stile = blockIdx.x, b = blockIdx.y, proj = blockIdx.z;
    const float* W = (proj == 0) ? Wq : (proj == 1 ? Wk : Wv);
    const int tid = threadIdx.x;
    const int tx = tid & 15, ty = tid >> 4;

    for (int i = tid; i < 128 * 128; i += 256) {
        int o = i >> 7, c = i & 127;
        Wt[c][o] = W[i];
    }

    const int s0 = stile * 64;
    const float* xb = x + (size_t)b * C_ * SPAT;

    float acc[8][4];
    #pragma unroll
    for (int i = 0; i < 8; i++)
        #pragma unroll
        for (int j = 0; j < 4; j++) acc[i][j] = 0.f;

    for (int c0 = 0; c0 < 128; c0 += 16) {
        __syncthreads();  // Xs reuse barrier (also covers Wt load on iter 0)
        for (int i = tid; i < 16 * 64; i += 256) {
            int cc = i >> 6, ss = i & 63;
            Xs[cc][ss] = xb[(size_t)(c0 + cc) * SPAT + s0 + ss];
        }
        __syncthreads();
        #pragma unroll
        for (int cc = 0; cc < 16; cc++) {
            float4 xv = *(const float4*)&Xs[cc][tx * 4];
            float4 wa = *(const float4*)&Wt[c0 + cc][ty * 8];
            float4 wb = *(const float4*)&Wt[c0 + cc][ty * 8 + 4];
            acc[0][0] += wa.x * xv.x; acc[0][1] += wa.x * xv.y; acc[0][2] += wa.x * xv.z; acc[0][3] += wa.x * xv.w;
            acc[1][0] += wa.y * xv.x; acc[1][1] += wa.y * xv.y; acc[1][2] += wa.y * xv.z; acc[1][3] += wa.y * xv.w;
            acc[2][0] += wa.z * xv.x; acc[2][1] += wa.z * xv.y; acc[2][2] += wa.z * xv.z; acc[2][3] += wa.z * xv.w;
            acc[3][0] += wa.w * xv.x; acc[3][1] += wa.w * xv.y; acc[3][2] += wa.w * xv.z; acc[3][3] += wa.w * xv.w;
            acc[4][0] += wb.x * xv.x; acc[4][1] += wb.x * xv.y; acc[4][2] += wb.x * xv.z; acc[4][3] += wb.x * xv.w;
            acc[5][0] += wb.y * xv.x; acc[5][1] += wb.y * xv.y; acc[5][2] += wb.y * xv.z; acc[5][3] += wb.y * xv.w;
            acc[6][0] += wb.z * xv.x; acc[6][1] += wb.z * xv.y; acc[6][2] += wb.z * xv.z; acc[6][3] += wb.z * xv.w;
            acc[7][0] += wb.w * xv.x; acc[7][1] += wb.w * xv.y; acc[7][2] += wb.w * xv.z; acc[7][3] += wb.w * xv.w;
        }
    }

    // store y + per-thread group partials (groups of 4 channels: o/4)
    float* y = &g_y[proj][b][0][0];
    float gs[2] = {0.f, 0.f}, gq2[2] = {0.f, 0.f};
    #pragma unroll
    for (int i = 0; i < 8; i++) {
        int o = ty * 8 + i;
        float4 v = make_float4(acc[i][0], acc[i][1], acc[i][2], acc[i][3]);
        *(float4*)&y[(size_t)o * SPAT + s0 + tx * 4] = v;
        int gi = i >> 2;
        gs[gi]  += v.x + v.y + v.z + v.w;
        gq2[gi] += v.x * v.x + v.y * v.y + v.z * v.z + v.w * v.w;
    }
    // deterministic tree reduce across the 16 tx lanes (lane halves 0-15 / 16-31)
    #pragma unroll
    for (int off = 8; off; off >>= 1) {
        gs[0]  += __shfl_down_sync(0xffffffffu, gs[0],  off);
        gs[1]  += __shfl_down_sync(0xffffffffu, gs[1],  off);
        gq2[0] += __shfl_down_sync(0xffffffffu, gq2[0], off);
        gq2[1] += __shfl_down_sync(0xffffffffu, gq2[1], off);
    }
    if (tx == 0) {
        int g0 = ty * 2;
        g_part[proj][b][g0    ][stile][0] = gs[0];
        g_part[proj][b][g0    ][stile][1] = gq2[0];
        g_part[proj][b][g0 + 1][stile][0] = gs[1];
        g_part[proj][b][g0 + 1][stile][1] = gq2[1];
    }
}

// ================= K2: finalize GN stats =====================================
// grid: (32 groups, B, 3 proj), block 256 (one thread per s-tile partial)
__global__ __launch_bounds__(256) void stats_kernel()
{
    const int g = blockIdx.x, b = blockIdx.y, proj = blockIdx.z;
    const int tid = threadIdx.x;
    float s = g_part[proj][b][g][tid][0];
    float q = g_part[proj][b][g][tid][1];
    __shared__ float ss[8], sq[8];
    #pragma unroll
    for (int off = 16; off; off >>= 1) {
        s += __shfl_down_sync(0xffffffffu, s, off);
        q += __shfl_down_sync(0xffffffffu, q, off);
    }
    if ((tid & 31) == 0) { ss[tid >> 5] = s; sq[tid >> 5] = q; }
    __syncthreads();
    if (tid == 0) {
        float S = 0.f, Q = 0.f;
        #pragma unroll
        for (int i = 0; i < 8; i++) { S += ss[i]; Q += sq[i]; }
        const float inv = 1.f / 65536.f;   // 4 channels * 16384 spatial
        float mu  = S * inv;
        float var = Q * inv - mu * mu;
        g_stats[proj][b][g][0] = mu;
        g_stats[proj][b][g][1] = rsqrtf(var + 1e-5f);
    }
}

// ================= K3: normalize + patchify + pool ===========================
// grid 16384 blocks x 256 thr; each 64-thread slice handles one (b,g,n) token.
__global__ __launch_bounds__(256) void patch_kernel(
    const float* __restrict__ gqg, const float* __restrict__ gqb,
    const float* __restrict__ gkg, const float* __restrict__ gkb,
    const float* __restrict__ gvg, const float* __restrict__ gvb)
{
    const int tid  = threadIdx.x;
    const int unit = blockIdx.x * 4 + (tid >> 6);   // (b,g,n) flat
    const int n = unit & 1023;
    const int g = (unit >> 10) & 31;
    const int b = unit >> 15;
    const int local = tid & 63;
    const int d = local >> 4, p = local & 15;
    const int c = g * 4 + d;
    const int ti = n >> 8, hi = (n >> 4) & 15, wi = n & 15;
    const int sh = p >> 2, sw = p & 3;
    const int s = ti * 4096 + (hi * 4 + sh) * 64 + wi * 4 + sw;

    const float yq = g_y[0][b][c][s];
    const float yk = g_y[1][b][c][s];
    const float yv = g_y[2][b][c][s];

    float nq = (yq - g_stats[0][b][g][0]) * g_stats[0][b][g][1] * gqg[c] + gqb[c];
    float nk = (yk - g_stats[1][b][g][0]) * g_stats[1][b][g][1] * gkg[c] + gkb[c];
    float nv = (yv - g_stats[2][b][g][0]) * g_stats[2][b][g][1] * gvg[c] + gvb[c];

    g_vp[b][g][n][d * 16 + p] = nv;

    // pool q,k over p (16 consecutive lanes) — deterministic shuffle tree
    #pragma unroll
    for (int off = 8; off; off >>= 1) {
        nq += __shfl_down_sync(0xffffffffu, nq, off);
        nk += __shfl_down_sync(0xffffffffu, nk, off);
    }
    if (p == 0) {
        g_qp[b][g][n][d] = nq * (1.f / 16.f);
        g_kp[b][g][n][d] = nk * (1.f / 16.f);
    }
}

// ================= K4: attention (logits + bias + softmax + AV) ==============
// grid (32 row-tiles, 32 g, 2 b), block 256, R=32 rows/CTA.
// dyn smem: kp[1024]f4 (16KB) + q[32]f4 (512B) + logits 32x1024 (128KB) + rsum[32]
#define ATTN_SMEM (16384 + 512 + 131072 + 128)

__global__ __launch_bounds__(256) void attn_kernel(
    const float* __restrict__ rel_table,
    const int*   __restrict__ rel_index,
    float*       __restrict__ out)
{
    extern __shared__ float smem[];
    float4* kp_s = (float4*)smem;            // 1024 float4
    float4* q_s  = (float4*)(smem + 4096);   // 32 float4
    float*  lg   = smem + 4096 + 128;        // 32 * 1024
    float*  rsum = lg + 32768;               // 32

    const int ntile = blockIdx.x, g = blockIdx.y, b = blockIdx.z;
    const int n0 = ntile * 32;
    const int tid = threadIdx.x;

    const float4* kp = (const float4*)&g_kp[b][g][0][0];
    for (int i = tid; i < 1024; i += 256) kp_s[i] = kp[i];
    if (tid < 32) q_s[tid] = ((const float4*)&g_qp[b][g][0][0])[n0 + tid];
    __syncthreads();

    // ---- logits + relative-position bias ----
    const float* tbl = rel_table + g * TBL_;
    for (int idx = tid; idx < 32 * 1024; idx += 256) {
        int r = idx >> 10, m = idx & 1023;
        float4 qv = q_s[r], kv = kp_s[m];
        float dot = qv.x * kv.x + qv.y * kv.y + qv.z * kv.z + qv.w * kv.w;
        int ri = rel_index[(size_t)(n0 + r) * 1024 + m];
        lg[idx] = 0.5f * dot + __ldg(&tbl[ri]);   // scale = 1/sqrt(4)
    }
    __syncthreads();

    // ---- softmax (un-normalized exp in smem; 1/sum folded into epilogue) ----
    const int warp = tid >> 5, lane = tid & 31;
    for (int rr = 0; rr < 4; rr++) {
        const int r = warp * 4 + rr;
        float* row = lg + (r << 10);
        float mx = -1e30f;
        for (int m = lane; m < 1024; m += 32) mx = fmaxf(mx, row[m]);
        #pragma unroll
        for (int off = 16; off; off >>= 1) mx = fmaxf(mx, __shfl_xor_sync(0xffffffffu, mx, off));
        float s = 0.f;
        for (int m = lane; m < 1024; m += 32) {
            float e = __expf(row[m] - mx);
            row[m] = e;
            s += e;
        }
        #pragma unroll
        for (int off = 16; off; off >>= 1) s += __shfl_xor_sync(0xffffffffu, s, off);
        if (lane == 0) rsum[r] = 1.f / s;
    }
    __syncthreads();

    // ---- AV: out[r][dp] = sum_m attn[r][m] * vp[m][dp] ----
    const int dp = tid & 63, rg = tid >> 6;   // 4 row-groups x 8 rows
    const float* vp = &g_vp[b][g][0][0];
    float acc[8];
    #pragma unroll
    for (int i = 0; i < 8; i++) acc[i] = 0.f;
    #pragma unroll 4
    for (int m = 0; m < 1024; m++) {
        float v = vp[(size_t)m * 64 + dp];
        #pragma unroll
        for (int rr = 0; rr < 8; rr++)
            acc[rr] += lg[((rg * 8 + rr) << 10) + m] * v;
    }

    // ---- epilogue: normalize + scatter to (B,C,T,H,W) ----
    const int d = dp >> 4, p = dp & 15, sh = p >> 2, sw = p & 3;
    const int c = g * 4 + d;
    #pragma unroll
    for (int rr = 0; rr < 8; rr++) {
        int r = rg * 8 + rr, n = n0 + r;
        int ti = n >> 8, hi = (n >> 4) & 15, wi = n & 15;
        size_t o = ((size_t)((b * 128 + c) * 4 + ti) * 64 + hi * 4 + sh) * 64 + wi * 4 + sw;
        out[o] = acc[rr] * rsum[r];
    }
}

// ============================ launcher =======================================
extern "C" void kernel_launch(void* const* d_in, const int* in_sizes, int n_in,
                              void* d_out, int out_size)
{
    const float* x   = (const float*)d_in[0];
    const float* Wq  = (const float*)d_in[1];
    const float* Wk  = (const float*)d_in[2];
    const float* Wv  = (const float*)d_in[3];
    const float* gqg = (const float*)d_in[4];
    const float* gqb = (const float*)d_in[5];
    const float* gkg = (const float*)d_in[6];
    const float* gkb = (const float*)d_in[7];
    const float* gvg = (const float*)d_in[8];
    const float* gvb = (const float*)d_in[9];
    const float* rel_table = (const float*)d_in[10];
    const int*   rel_index = (const int*)d_in[11];
    float* out = (float*)d_out;

    cudaFuncSetAttribute(attn_kernel, cudaFuncAttributeMaxDynamicSharedMemorySize, ATTN_SMEM);

    proj_kernel<<<dim3(256, B_, 3), 256>>>(x, Wq, Wk, Wv);
    stats_kernel<<<dim3(NH_, B_, 3), 256>>>();
    patch_kernel<<<16384, 256>>>(gqg, gqb, gkg, gkb, gvg, gvb);
    attn_kernel<<<dim3(32, NH_, B_), 256, ATTN_SMEM>>>(rel_table, rel_index, out);
}

// round 4
// speedup vs baseline: 1.4929x; 1.4929x over previous
#include <cuda_runtime.h>
#include <math.h>

// ---------------- problem constants ----------------
#define B_    2
#define C_    128
#define T_    4
#define NH_   32        // heads == groupnorm groups
#define DH_   4         // head dim
#define SPAT  16384     // T*H*W
#define NTOK  1024      // T * (H/4) * (W/4)
#define PP_   16        // pixels per patch
#define TBL_  6727      // (2T-1)*(2h-1)*(2w-1)

typedef unsigned long long ull;

// packed fp32x2 helpers (sm_103a FFMA2 path; bit-identical rounding to scalar FFMA)
__device__ __forceinline__ ull pack2(float a) {
    ull r;
    unsigned int ai = __float_as_uint(a);
    asm("mov.b64 %0, {%1, %1};" : "=l"(r) : "r"(ai));
    return r;
}
__device__ __forceinline__ void ffma2(ull& d, ull a, ull b) {
    asm("fma.rn.f32x2 %0, %1, %2, %0;" : "+l"(d) : "l"(a), "l"(b));
}
__device__ __forceinline__ float2 unpack2(ull v) {
    float2 f;
    unsigned int lo, hi;
    asm("mov.b64 {%0, %1}, %2;" : "=r"(lo), "=r"(hi) : "l"(v));
    f.x = __uint_as_float(lo); f.y = __uint_as_float(hi);
    return f;
}

// ---------------- scratch (device globals; no runtime alloc) ----------------
__device__ float g_y[3][B_][C_][SPAT];        // raw q/k/v projections (50 MB)
__device__ float g_part[3][B_][NH_][256][2];  // per-s-tile partial (sum, sumsq)
__device__ float g_stats[3][B_][NH_][2];      // (mean, rstd)
__device__ float g_qp[B_][NH_][NTOK][DH_];    // pooled queries  (float4/token)
__device__ float g_kp[B_][NH_][NTOK][DH_];    // pooled keys
__device__ float g_vp[B_][NH_][NTOK][DH_*PP_];// full-res values [m][d*16+p]

// ================= K1: 1x1x1 conv projections + GN partial stats ============
// grid: (256 s-tiles, B, 3 proj), block 256. Tile: 128 o x 64 s. FFMA2 inner.
__global__ __launch_bounds__(256) void proj_kernel(
    const float* __restrict__ x,
    const float* __restrict__ Wq,
    const float* __restrict__ Wk,
    const float* __restrict__ Wv)
{
    __shared__ float Wt[128][132];   // W transposed [c][o], padded
    __shared__ float Xs[16][68];     // x chunk [c][s], padded

    const int stile = blockIdx.x, b = blockIdx.y, proj = blockIdx.z;
    const float* W = (proj == 0) ? Wq : (proj == 1 ? Wk : Wv);
    const int tid = threadIdx.x;
    const int tx = tid & 15, ty = tid >> 4;

    for (int i = tid; i < 128 * 128; i += 256) {
        int o = i >> 7, c = i & 127;
        Wt[c][o] = W[i];
    }

    const int s0 = stile * 64;
    const float* xb = x + (size_t)b * C_ * SPAT;

    ull accL[8], accH[8];
    #pragma unroll
    for (int i = 0; i < 8; i++) { accL[i] = 0ull; accH[i] = 0ull; }

    for (int c0 = 0; c0 < 128; c0 += 16) {
        __syncthreads();  // Xs reuse barrier (also covers Wt load on iter 0)
        for (int i = tid; i < 16 * 64; i += 256) {
            int cc = i >> 6, ss = i & 63;
            Xs[cc][ss] = xb[(size_t)(c0 + cc) * SPAT + s0 + ss];
        }
        __syncthreads();
        #pragma unroll
        for (int cc = 0; cc < 16; cc++) {
            float4 xv = *(const float4*)&Xs[cc][tx * 4];
            ull xL = ((const ull*)&xv)[0];
            ull xH = ((const ull*)&xv)[1];
            float4 wa = *(const float4*)&Wt[c0 + cc][ty * 8];
            float4 wb = *(const float4*)&Wt[c0 + cc][ty * 8 + 4];
            ull p0 = pack2(wa.x), p1 = pack2(wa.y), p2 = pack2(wa.z), p3 = pack2(wa.w);
            ull p4 = pack2(wb.x), p5 = pack2(wb.y), p6 = pack2(wb.z), p7 = pack2(wb.w);
            ffma2(accL[0], p0, xL); ffma2(accH[0], p0, xH);
            ffma2(accL[1], p1, xL); ffma2(accH[1], p1, xH);
            ffma2(accL[2], p2, xL); ffma2(accH[2], p2, xH);
            ffma2(accL[3], p3, xL); ffma2(accH[3], p3, xH);
            ffma2(accL[4], p4, xL); ffma2(accH[4], p4, xH);
            ffma2(accL[5], p5, xL); ffma2(accH[5], p5, xH);
            ffma2(accL[6], p6, xL); ffma2(accH[6], p6, xH);
            ffma2(accL[7], p7, xL); ffma2(accH[7], p7, xH);
        }
    }

    // store y + per-thread group partials (groups of 4 channels: o/4)
    float* y = &g_y[proj][b][0][0];
    float gs[2] = {0.f, 0.f}, gq2[2] = {0.f, 0.f};
    #pragma unroll
    for (int i = 0; i < 8; i++) {
        int o = ty * 8 + i;
        float2 lo = unpack2(accL[i]);
        float2 hi = unpack2(accH[i]);
        float4 v = make_float4(lo.x, lo.y, hi.x, hi.y);
        *(float4*)&y[(size_t)o * SPAT + s0 + tx * 4] = v;
        int gi = i >> 2;
        gs[gi]  += v.x + v.y + v.z + v.w;
        gq2[gi] += v.x * v.x + v.y * v.y + v.z * v.z + v.w * v.w;
    }
    // deterministic tree reduce across the 16 tx lanes
    #pragma unroll
    for (int off = 8; off; off >>= 1) {
        gs[0]  += __shfl_down_sync(0xffffffffu, gs[0],  off);
        gs[1]  += __shfl_down_sync(0xffffffffu, gs[1],  off);
        gq2[0] += __shfl_down_sync(0xffffffffu, gq2[0], off);
        gq2[1] += __shfl_down_sync(0xffffffffu, gq2[1], off);
    }
    if (tx == 0) {
        int g0 = ty * 2;
        g_part[proj][b][g0    ][stile][0] = gs[0];
        g_part[proj][b][g0    ][stile][1] = gq2[0];
        g_part[proj][b][g0 + 1][stile][0] = gs[1];
        g_part[proj][b][g0 + 1][stile][1] = gq2[1];
    }
}

// ================= K2: finalize GN stats =====================================
__global__ __launch_bounds__(256) void stats_kernel()
{
    const int g = blockIdx.x, b = blockIdx.y, proj = blockIdx.z;
    const int tid = threadIdx.x;
    float s = g_part[proj][b][g][tid][0];
    float q = g_part[proj][b][g][tid][1];
    __shared__ float ss[8], sq[8];
    #pragma unroll
    for (int off = 16; off; off >>= 1) {
        s += __shfl_down_sync(0xffffffffu, s, off);
        q += __shfl_down_sync(0xffffffffu, q, off);
    }
    if ((tid & 31) == 0) { ss[tid >> 5] = s; sq[tid >> 5] = q; }
    __syncthreads();
    if (tid == 0) {
        float S = 0.f, Q = 0.f;
        #pragma unroll
        for (int i = 0; i < 8; i++) { S += ss[i]; Q += sq[i]; }
        const float inv = 1.f / 65536.f;   // 4 channels * 16384 spatial
        float mu  = S * inv;
        float var = Q * inv - mu * mu;
        g_stats[proj][b][g][0] = mu;
        g_stats[proj][b][g][1] = rsqrtf(var + 1e-5f);
    }
}

// ================= K3: normalize + patchify + pool ===========================
__global__ __launch_bounds__(256) void patch_kernel(
    const float* __restrict__ gqg, const float* __restrict__ gqb,
    const float* __restrict__ gkg, const float* __restrict__ gkb,
    const float* __restrict__ gvg, const float* __restrict__ gvb)
{
    const int tid  = threadIdx.x;
    const int unit = blockIdx.x * 4 + (tid >> 6);   // (b,g,n) flat
    const int n = unit & 1023;
    const int g = (unit >> 10) & 31;
    const int b = unit >> 15;
    const int local = tid & 63;
    const int d = local >> 4, p = local & 15;
    const int c = g * 4 + d;
    const int ti = n >> 8, hi = (n >> 4) & 15, wi = n & 15;
    const int sh = p >> 2, sw = p & 3;
    const int s = ti * 4096 + (hi * 4 + sh) * 64 + wi * 4 + sw;

    const float yq = g_y[0][b][c][s];
    const float yk = g_y[1][b][c][s];
    const float yv = g_y[2][b][c][s];

    float nq = (yq - g_stats[0][b][g][0]) * g_stats[0][b][g][1] * gqg[c] + gqb[c];
    float nk = (yk - g_stats[1][b][g][0]) * g_stats[1][b][g][1] * gkg[c] + gkb[c];
    float nv = (yv - g_stats[2][b][g][0]) * g_stats[2][b][g][1] * gvg[c] + gvb[c];

    g_vp[b][g][n][d * 16 + p] = nv;

    #pragma unroll
    for (int off = 8; off; off >>= 1) {
        nq += __shfl_down_sync(0xffffffffu, nq, off);
        nk += __shfl_down_sync(0xffffffffu, nk, off);
    }
    if (p == 0) {
        g_qp[b][g][n][d] = nq * (1.f / 16.f);
        g_kp[b][g][n][d] = nk * (1.f / 16.f);
    }
}

// ================= K4: attention (logits + bias + softmax + AV) ==============
// grid (32 row-tiles, 32 g, 2 b), block 256 (16x16), R=32 rows/CTA.
// smem layout (floats): kp[4096] | q[128] | lg[32*1032] | rsum[32] | vp_s[64*64]
#define LGS     1032
#define OFF_Q   4096
#define OFF_LG  4224
#define OFF_RS  (OFF_LG + 32 * LGS)       // 37248
#define OFF_VP  (OFF_RS + 32)             // 37280 (16B aligned)
#define ATTN_SMEM ((OFF_VP + 64 * 64) * 4)  // 165504 bytes

__global__ __launch_bounds__(256) void attn_kernel(
    const float* __restrict__ rel_table,
    const int*   __restrict__ rel_index,
    float*       __restrict__ out)
{
    extern __shared__ float smem[];
    float4* kp_s = (float4*)smem;            // 1024 float4
    float4* q_s  = (float4*)(smem + OFF_Q);  // 32 float4
    float*  lg   = smem + OFF_LG;            // 32 rows, stride 1032
    float*  rsum = smem + OFF_RS;            // 32
    float*  vp_s = smem + OFF_VP;            // 64 x 64 tile

    const int ntile = blockIdx.x, g = blockIdx.y, b = blockIdx.z;
    const int n0 = ntile * 32;
    const int tid = threadIdx.x;
    const int tx = tid & 15, ty = tid >> 4;

    // prefetch first vp tile into registers (hides L2 latency behind logits)
    const float4* vp4 = (const float4*)&g_vp[b][g][0][0];
    float4 pf[4];
    #pragma unroll
    for (int k = 0; k < 4; k++) pf[k] = vp4[tid + k * 256];

    const float4* kp = (const float4*)&g_kp[b][g][0][0];
    for (int i = tid; i < 1024; i += 256) kp_s[i] = kp[i];
    if (tid < 32) q_s[tid] = ((const float4*)&g_qp[b][g][0][0])[n0 + tid];
    __syncthreads();

    // ---- logits + relative-position bias (unroll 8 -> 8 LDGs in flight) ----
    const float* tbl = rel_table + g * TBL_;
    #pragma unroll 8
    for (int idx = tid; idx < 32 * 1024; idx += 256) {
        int r = idx >> 10, m = idx & 1023;
        float4 qv = q_s[r], kv = kp_s[m];
        float dot = qv.x * kv.x + qv.y * kv.y + qv.z * kv.z + qv.w * kv.w;
        int ri = rel_index[(size_t)(n0 + r) * 1024 + m];
        lg[r * LGS + m] = 0.5f * dot + __ldg(&tbl[ri]);   // scale = 1/sqrt(4)
    }
    __syncthreads();

    // ---- softmax (un-normalized exp in smem; 1/sum folded into epilogue) ----
    {
        const int warp = tid >> 5, lane = tid & 31;
        for (int rr = 0; rr < 4; rr++) {
            const int r = warp * 4 + rr;
            float* row = lg + r * LGS;
            float mx = -1e30f;
            for (int m = lane; m < 1024; m += 32) mx = fmaxf(mx, row[m]);
            #pragma unroll
            for (int off = 16; off; off >>= 1) mx = fmaxf(mx, __shfl_xor_sync(0xffffffffu, mx, off));
            float s = 0.f;
            for (int m = lane; m < 1024; m += 32) {
                float e = __expf(row[m] - mx);
                row[m] = e;
                s += e;
            }
            #pragma unroll
            for (int off = 16; off; off >>= 1) s += __shfl_xor_sync(0xffffffffu, s, off);
            if (lane == 0) rsum[r] = 1.f / s;
        }
    }

    // ---- AV: 16 m-tiles of 64, vp staged in smem, FFMA2 inner ----
    // thread (tx,ty): rows r0=ty*2, r0+1; cols dp = tx*4 .. tx*4+3
    const int r0 = ty * 2;
    const float* lgr0 = lg + r0 * LGS;
    const float* lgr1 = lg + (r0 + 1) * LGS;
    ull accL0 = 0, accH0 = 0, accL1 = 0, accH1 = 0;

    for (int t = 0; t < 16; t++) {
        __syncthreads();                     // previous tile fully consumed
        float4* vs4 = (float4*)vp_s;
        #pragma unroll
        for (int k = 0; k < 4; k++) vs4[tid + k * 256] = pf[k];
        __syncthreads();
        if (t < 15) {
            #pragma unroll
            for (int k = 0; k < 4; k++) pf[k] = vp4[(t + 1) * 1024 + tid + k * 256];
        }
        const int mg0 = t * 64;
        #pragma unroll 4
        for (int ml = 0; ml < 64; ml++) {
            float a0 = lgr0[mg0 + ml];
            float a1 = lgr1[mg0 + ml];
            float4 v = *(const float4*)&vp_s[ml * 64 + tx * 4];
            ull vL = ((const ull*)&v)[0];
            ull vH = ((const ull*)&v)[1];
            ull pa0 = pack2(a0), pa1 = pack2(a1);
            ffma2(accL0, pa0, vL); ffma2(accH0, pa0, vH);
            ffma2(accL1, pa1, vL); ffma2(accH1, pa1, vH);
        }
    }

    // ---- epilogue: normalize + float4 scatter to (B,C,T,H,W) ----
    const int d = tx >> 2, sh = tx & 3;
    const int c = g * 4 + d;
    #pragma unroll
    for (int rr = 0; rr < 2; rr++) {
        int r = r0 + rr, n = n0 + r;
        int ti = n >> 8, hi = (n >> 4) & 15, wi = n & 15;
        float rs = rsum[r];
        float2 lo = unpack2(rr ? accL1 : accL0);
        float2 hi2 = unpack2(rr ? accH1 : accH0);
        float4 o = make_float4(lo.x * rs, lo.y * rs, hi2.x * rs, hi2.y * rs);
        size_t ofs = ((size_t)((b * 128 + c) * 4 + ti) * 64 + hi * 4 + sh) * 64 + wi * 4;
        *(float4*)&out[ofs] = o;
    }
}

// ============================ launcher =======================================
extern "C" void kernel_launch(void* const* d_in, const int* in_sizes, int n_in,
                              void* d_out, int out_size)
{
    const float* x   = (const float*)d_in[0];
    const float* Wq  = (const float*)d_in[1];
    const float* Wk  = (const float*)d_in[2];
    const float* Wv  = (const float*)d_in[3];
    const float* gqg = (const float*)d_in[4];
    const float* gqb = (const float*)d_in[5];
    const float* gkg = (const float*)d_in[6];
    const float* gkb = (const float*)d_in[7];
    const float* gvg = (const float*)d_in[8];
    const float* gvb = (const float*)d_in[9];
    const float* rel_table = (const float*)d_in[10];
    const int*   rel_index = (const int*)d_in[11];
    float* out = (float*)d_out;

    cudaFuncSetAttribute(attn_kernel, cudaFuncAttributeMaxDynamicSharedMemorySize, ATTN_SMEM);

    proj_kernel<<<dim3(256, B_, 3), 256>>>(x, Wq, Wk, Wv);
    stats_kernel<<<dim3(NH_, B_, 3), 256>>>();
    patch_kernel<<<16384, 256>>>(gqg, gqb, gkg, gkb, gvg, gvb);
    attn_kernel<<<dim3(32, NH_, B_), 256, ATTN_SMEM>>>(rel_table, rel_index, out);
}

// round 8
// speedup vs baseline: 4.2204x; 2.8270x over previous
#include <cuda_runtime.h>
#include <cuda_bf16.h>
#include <math.h>
#include <cstdint>

// ---------------- problem constants ----------------
#define B_    2
#define C_    128
#define NH_   32
#define DH_   4
#define SPAT  16384
#define NTOK  1024
#define TBL_  6727

typedef unsigned long long ull;
typedef unsigned int uint;

// ---------------- packed fp32x2 helpers ----------------
__device__ __forceinline__ ull pack2(float a) {
    ull r; uint ai = __float_as_uint(a);
    asm("mov.b64 %0, {%1, %1};" : "=l"(r) : "r"(ai));
    return r;
}
__device__ __forceinline__ ull packf2(float lo, float hi) {
    ull r;
    asm("mov.b64 %0, {%1, %2};" : "=l"(r) : "f"(lo), "f"(hi));
    return r;
}
__device__ __forceinline__ void ffma2(ull& d, ull a, ull b) {
    asm("fma.rn.f32x2 %0, %1, %2, %0;" : "+l"(d) : "l"(a), "l"(b));
}
__device__ __forceinline__ float2 unpack2(ull v) {
    float2 f; uint lo, hi;
    asm("mov.b64 {%0, %1}, %2;" : "=r"(lo), "=r"(hi) : "l"(v));
    f.x = __uint_as_float(lo); f.y = __uint_as_float(hi);
    return f;
}
__device__ __forceinline__ float ex2f(float x) {
    float r; asm("ex2.approx.f32 %0, %1;" : "=f"(r) : "f"(x)); return r;
}
// bf16x2 pack: first operand -> hi half, second -> lo half
__device__ __forceinline__ uint cvt_hl(float hi, float lo) {
    uint d;
    asm("cvt.rn.bf16x2.f32 %0, %1, %2;" : "=r"(d) : "f"(hi), "f"(lo));
    return d;
}
// mma.sync m16n8k16 row.col f32.bf16.bf16.f32 (sm_80+; no 'a'-gated features)
__device__ __forceinline__ void mma16816(float* c, const uint* a, uint b0, uint b1) {
    asm volatile(
        "mma.sync.aligned.m16n8k16.row.col.f32.bf16.bf16.f32 "
        "{%0,%1,%2,%3}, {%4,%5,%6,%7}, {%8,%9}, {%0,%1,%2,%3};"
        : "+f"(c[0]), "+f"(c[1]), "+f"(c[2]), "+f"(c[3])
        : "r"(a[0]), "r"(a[1]), "r"(a[2]), "r"(a[3]), "r"(b0), "r"(b1));
}
// split fp32 -> (hi, lo) bf16 pairs
__device__ __forceinline__ void split_pack(float e0, float e1, uint& h, uint& l) {
    unsigned short h0 = __bfloat16_as_ushort(__float2bfloat16(e0));
    unsigned short h1 = __bfloat16_as_ushort(__float2bfloat16(e1));
    h = ((uint)h1 << 16) | h0;
    float f0 = __bfloat162float(__ushort_as_bfloat16(h0));
    float f1 = __bfloat162float(__ushort_as_bfloat16(h1));
    unsigned short l0 = __bfloat16_as_ushort(__float2bfloat16(e0 - f0));
    unsigned short l1 = __bfloat16_as_ushort(__float2bfloat16(e1 - f1));
    l = ((uint)l1 << 16) | l0;
}

// ---------------- scratch ----------------
__device__ float g_y[3][B_][C_][SPAT];
__device__ float g_part[3][B_][NH_][256][2];
__device__ float g_stats[3][B_][NH_][2];
__device__ float g_qp[B_][NH_][NTOK][DH_];
__device__ float g_kp[B_][NH_][NTOK][DH_];
__device__ float g_vp[B_][NH_][NTOK][64];       // fp32 [n][dp]
__device__ uint  g_vph[B_ * NH_][64][512];      // bf16 hi, [dp][m-pair]
__device__ uint  g_vpl[B_ * NH_][64][512];      // bf16 lo
__device__ float g_tbl2[NH_][TBL_];             // rel_table * log2(e)

// ================= K1: projections + GN partial stats ========================
__global__ __launch_bounds__(256) void proj_kernel(
    const float* __restrict__ x, const float* __restrict__ Wq,
    const float* __restrict__ Wk, const float* __restrict__ Wv)
{
    __shared__ float Wt[128][132];
    __shared__ float Xs[16][68];

    const int stile = blockIdx.x, b = blockIdx.y, proj = blockIdx.z;
    const float* W = (proj == 0) ? Wq : (proj == 1 ? Wk : Wv);
    const int tid = threadIdx.x;
    const int tx = tid & 15, ty = tid >> 4;

    for (int i = tid; i < 128 * 128; i += 256) {
        int o = i >> 7, c = i & 127;
        Wt[c][o] = W[i];
    }
    const int s0 = stile * 64;
    const float* xb = x + (size_t)b * C_ * SPAT;

    ull accL[8], accH[8];
    #pragma unroll
    for (int i = 0; i < 8; i++) { accL[i] = 0ull; accH[i] = 0ull; }

    for (int c0 = 0; c0 < 128; c0 += 16) {
        __syncthreads();
        for (int i = tid; i < 16 * 64; i += 256) {
            int cc = i >> 6, ss = i & 63;
            Xs[cc][ss] = xb[(size_t)(c0 + cc) * SPAT + s0 + ss];
        }
        __syncthreads();
        #pragma unroll
        for (int cc = 0; cc < 16; cc++) {
            float4 xv = *(const float4*)&Xs[cc][tx * 4];
            ull xL = ((const ull*)&xv)[0];
            ull xH = ((const ull*)&xv)[1];
            float4 wa = *(const float4*)&Wt[c0 + cc][ty * 8];
            float4 wb = *(const float4*)&Wt[c0 + cc][ty * 8 + 4];
            ull p0 = pack2(wa.x), p1 = pack2(wa.y), p2 = pack2(wa.z), p3 = pack2(wa.w);
            ull p4 = pack2(wb.x), p5 = pack2(wb.y), p6 = pack2(wb.z), p7 = pack2(wb.w);
            ffma2(accL[0], p0, xL); ffma2(accH[0], p0, xH);
            ffma2(accL[1], p1, xL); ffma2(accH[1], p1, xH);
            ffma2(accL[2], p2, xL); ffma2(accH[2], p2, xH);
            ffma2(accL[3], p3, xL); ffma2(accH[3], p3, xH);
            ffma2(accL[4], p4, xL); ffma2(accH[4], p4, xH);
            ffma2(accL[5], p5, xL); ffma2(accH[5], p5, xH);
            ffma2(accL[6], p6, xL); ffma2(accH[6], p6, xH);
            ffma2(accL[7], p7, xL); ffma2(accH[7], p7, xH);
        }
    }

    float* y = &g_y[proj][b][0][0];
    float gs[2] = {0.f, 0.f}, gq2[2] = {0.f, 0.f};
    #pragma unroll
    for (int i = 0; i < 8; i++) {
        int o = ty * 8 + i;
        float2 lo = unpack2(accL[i]);
        float2 hi = unpack2(accH[i]);
        float4 v = make_float4(lo.x, lo.y, hi.x, hi.y);
        *(float4*)&y[(size_t)o * SPAT + s0 + tx * 4] = v;
        int gi = i >> 2;
        gs[gi]  += v.x + v.y + v.z + v.w;
        gq2[gi] += v.x * v.x + v.y * v.y + v.z * v.z + v.w * v.w;
    }
    #pragma unroll
    for (int off = 8; off; off >>= 1) {
        gs[0]  += __shfl_down_sync(0xffffffffu, gs[0],  off);
        gs[1]  += __shfl_down_sync(0xffffffffu, gs[1],  off);
        gq2[0] += __shfl_down_sync(0xffffffffu, gq2[0], off);
        gq2[1] += __shfl_down_sync(0xffffffffu, gq2[1], off);
    }
    if (tx == 0) {
        int g0 = ty * 2;
        g_part[proj][b][g0    ][stile][0] = gs[0];
        g_part[proj][b][g0    ][stile][1] = gq2[0];
        g_part[proj][b][g0 + 1][stile][0] = gs[1];
        g_part[proj][b][g0 + 1][stile][1] = gq2[1];
    }
}

// ================= K2: finalize GN stats =====================================
__global__ __launch_bounds__(256) void stats_kernel()
{
    const int g = blockIdx.x, b = blockIdx.y, proj = blockIdx.z;
    const int tid = threadIdx.x;
    float s = g_part[proj][b][g][tid][0];
    float q = g_part[proj][b][g][tid][1];
    __shared__ float ss[8], sq[8];
    #pragma unroll
    for (int off = 16; off; off >>= 1) {
        s += __shfl_down_sync(0xffffffffu, s, off);
        q += __shfl_down_sync(0xffffffffu, q, off);
    }
    if ((tid & 31) == 0) { ss[tid >> 5] = s; sq[tid >> 5] = q; }
    __syncthreads();
    if (tid == 0) {
        float S = 0.f, Q = 0.f;
        #pragma unroll
        for (int i = 0; i < 8; i++) { S += ss[i]; Q += sq[i]; }
        const float inv = 1.f / 65536.f;
        float mu  = S * inv;
        float var = Q * inv - mu * mu;
        g_stats[proj][b][g][0] = mu;
        g_stats[proj][b][g][1] = rsqrtf(var + 1e-5f);
    }
}

// ================= K3: normalize + patchify + pool ===========================
__global__ __launch_bounds__(256) void patch_kernel(
    const float* __restrict__ gqg, const float* __restrict__ gqb,
    const float* __restrict__ gkg, const float* __restrict__ gkb,
    const float* __restrict__ gvg, const float* __restrict__ gvb)
{
    const int tid  = threadIdx.x;
    const int unit = blockIdx.x * 4 + (tid >> 6);
    const int n = unit & 1023;
    const int g = (unit >> 10) & 31;
    const int b = unit >> 15;
    const int local = tid & 63;
    const int d = local >> 4, p = local & 15;
    const int c = g * 4 + d;
    const int ti = n >> 8, hi = (n >> 4) & 15, wi = n & 15;
    const int sh = p >> 2, sw = p & 3;
    const int s = ti * 4096 + (hi * 4 + sh) * 64 + wi * 4 + sw;

    const float yq = g_y[0][b][c][s];
    const float yk = g_y[1][b][c][s];
    const float yv = g_y[2][b][c][s];

    float nq = (yq - g_stats[0][b][g][0]) * g_stats[0][b][g][1] * gqg[c] + gqb[c];
    float nk = (yk - g_stats[1][b][g][0]) * g_stats[1][b][g][1] * gkg[c] + gkb[c];
    float nv = (yv - g_stats[2][b][g][0]) * g_stats[2][b][g][1] * gvg[c] + gvb[c];

    g_vp[b][g][n][d * 16 + p] = nv;

    #pragma unroll
    for (int off = 8; off; off >>= 1) {
        nq += __shfl_down_sync(0xffffffffu, nq, off);
        nk += __shfl_down_sync(0xffffffffu, nk, off);
    }
    if (p == 0) {
        g_qp[b][g][n][d] = nq * (1.f / 16.f);
        g_kp[b][g][n][d] = nk * (1.f / 16.f);
    }
}

// ================= K3b: vp -> transposed split-bf16 [dp][m] ==================
__global__ __launch_bounds__(256) void vtrans_kernel()
{
    __shared__ float ts[128][65];
    const int n0 = blockIdx.x * 128, bg = blockIdx.y;
    const int tid = threadIdx.x;
    const float* vp = &g_vp[0][0][0][0] + (size_t)bg * NTOK * 64;

    for (int i = tid; i < 128 * 64; i += 256) {
        int n = i >> 6, dp = i & 63;
        ts[n][dp] = vp[(size_t)(n0 + n) * 64 + dp];
    }
    __syncthreads();
    for (int i = tid; i < 64 * 64; i += 256) {
        int dp = i >> 6, j = i & 63;
        float v0 = ts[2 * j][dp], v1 = ts[2 * j + 1][dp];
        uint h, l;
        split_pack(v0, v1, h, l);
        g_vph[bg][dp][(n0 >> 1) + j] = h;
        g_vpl[bg][dp][(n0 >> 1) + j] = l;
    }
}

// ================= K3c: prescale bias table by log2(e) =======================
__global__ __launch_bounds__(256) void tblprep_kernel(const float* __restrict__ rel_table)
{
    const int g = blockIdx.x;
    for (int i = threadIdx.x; i < TBL_; i += 256)
        g_tbl2[g][i] = rel_table[g * TBL_ + i] * 1.4426950408889634f;
}

// ================= K4: attention via mma.sync bf16 (3-pass hi/lo) ============
// grid (8 mtiles, 32 g, 2 b), block 256 (8 warps). 128 rows/CTA, 16 rows/warp.
// smem: kp 16KB | q 2KB | Bhi 17408B | Blo 17408B = 53248B
#define ATT_SMEM 53248

__global__ __launch_bounds__(256, 2) void attn_kernel(
    const int* __restrict__ rel_index,
    float*     __restrict__ out)
{
    extern __shared__ float smem[];
    float4* kp_s = (float4*)smem;               // 1024 float4
    float4* q_s  = (float4*)(smem + 4096);      // 128 float4 (prescaled)
    uint*   bhs  = (uint*)(smem + 4608);        // 64 rows x 68 u32 (stride pad)
    uint*   bls  = bhs + 64 * 68;

    const int mtile = blockIdx.x, g = blockIdx.y, b = blockIdx.z;
    const int n0 = mtile * 128;
    const int bg = b * 32 + g;
    const int tid = threadIdx.x, wid = tid >> 5, lane = tid & 31;
    const int l = lane & 3, gid = lane >> 2;

    {
        const float4* kp = (const float4*)&g_kp[b][g][0][0];
        for (int i = tid; i < 1024; i += 256) kp_s[i] = kp[i];
        const float4* qp = (const float4*)&g_qp[b][g][0][0];
        const float QS = 0.72134752044448170f;   // 0.5 * log2(e)
        for (int i = tid; i < 128; i += 256) {
            float4 q = qp[n0 + i];
            q.x *= QS; q.y *= QS; q.z *= QS; q.w *= QS;
            q_s[i] = q;
        }
    }
    __syncthreads();

    // hoisted per-warp row data
    const int rb = wid * 16;
    float4 q0 = q_s[rb + gid], q1 = q_s[rb + gid + 8];
    ull q0x = pack2(q0.x), q0y = pack2(q0.y), q0z = pack2(q0.z), q0w = pack2(q0.w);
    ull q1x = pack2(q1.x), q1y = pack2(q1.y), q1z = pack2(q1.z), q1w = pack2(q1.w);
    const float* tbl = &g_tbl2[g][0];
    const int* ridx0 = rel_index + (size_t)(n0 + rb + gid) * 1024;
    const int* ridx1 = ridx0 + 8 * 1024;

    float acc[8][4];
    #pragma unroll
    for (int i = 0; i < 8; i++)
        #pragma unroll
        for (int j = 0; j < 4; j++) acc[i][j] = 0.f;
    float s0 = 0.f, s1 = 0.f;

    for (int c = 0; c < 8; c++) {
        // stage B chunk (128 k = 64 pairs per dp row), hi + lo
        for (int i = tid; i < 1024; i += 256) {
            int dp = i >> 4, j4 = i & 15;
            float4 vh = *(const float4*)&g_vph[bg][dp][c * 64 + j4 * 4];
            float4 vl = *(const float4*)&g_vpl[bg][dp][c * 64 + j4 * 4];
            *(float4*)&bhs[dp * 68 + j4 * 4] = vh;
            *(float4*)&bls[dp * 68 + j4 * 4] = vl;
        }
        __syncthreads();

        #pragma unroll
        for (int ks = 0; ks < 8; ks++) {
            const int m00 = c * 128 + ks * 16 + 2 * l;
            float4 kv00 = kp_s[m00],     kv01 = kp_s[m00 + 1];
            float4 kv10 = kp_s[m00 + 8], kv11 = kp_s[m00 + 9];

            int2 iA = __ldg((const int2*)(ridx0 + m00));
            int2 iB = __ldg((const int2*)(ridx0 + m00 + 8));
            int2 iC = __ldg((const int2*)(ridx1 + m00));
            int2 iD = __ldg((const int2*)(ridx1 + m00 + 8));
            ull d0a = packf2(__ldg(tbl + iA.x), __ldg(tbl + iA.y));
            ull d0b = packf2(__ldg(tbl + iB.x), __ldg(tbl + iB.y));
            ull d1a = packf2(__ldg(tbl + iC.x), __ldg(tbl + iC.y));
            ull d1b = packf2(__ldg(tbl + iD.x), __ldg(tbl + iD.y));

            ull kax = packf2(kv00.x, kv01.x), kay = packf2(kv00.y, kv01.y);
            ull kaz = packf2(kv00.z, kv01.z), kaw = packf2(kv00.w, kv01.w);
            ull kbx = packf2(kv10.x, kv11.x), kby = packf2(kv10.y, kv11.y);
            ull kbz = packf2(kv10.z, kv11.z), kbw = packf2(kv10.w, kv11.w);

            ffma2(d0a, q0x, kax); ffma2(d0a, q0y, kay); ffma2(d0a, q0z, kaz); ffma2(d0a, q0w, kaw);
            ffma2(d0b, q0x, kbx); ffma2(d0b, q0y, kby); ffma2(d0b, q0z, kbz); ffma2(d0b, q0w, kbw);
            ffma2(d1a, q1x, kax); ffma2(d1a, q1y, kay); ffma2(d1a, q1z, kaz); ffma2(d1a, q1w, kaw);
            ffma2(d1b, q1x, kbx); ffma2(d1b, q1y, kby); ffma2(d1b, q1z, kbz); ffma2(d1b, q1w, kbw);

            float2 f0a = unpack2(d0a), f0b = unpack2(d0b);
            float2 f1a = unpack2(d1a), f1b = unpack2(d1b);
            float e00 = ex2f(f0a.x), e01 = ex2f(f0a.y), e02 = ex2f(f0b.x), e03 = ex2f(f0b.y);
            float e10 = ex2f(f1a.x), e11 = ex2f(f1a.y), e12 = ex2f(f1b.x), e13 = ex2f(f1b.y);
            s0 += (e00 + e01) + (e02 + e03);
            s1 += (e10 + e11) + (e12 + e13);

            uint ah[4], al[4];
            ah[0] = cvt_hl(e01, e00);
            ah[1] = cvt_hl(e11, e10);
            ah[2] = cvt_hl(e03, e02);
            ah[3] = cvt_hl(e13, e12);
            {
                float g0 = __uint_as_float(ah[0] << 16), g1 = __uint_as_float(ah[0] & 0xffff0000u);
                al[0] = cvt_hl(e01 - g1, e00 - g0);
                g0 = __uint_as_float(ah[1] << 16); g1 = __uint_as_float(ah[1] & 0xffff0000u);
                al[1] = cvt_hl(e11 - g1, e10 - g0);
                g0 = __uint_as_float(ah[2] << 16); g1 = __uint_as_float(ah[2] & 0xffff0000u);
                al[2] = cvt_hl(e03 - g1, e02 - g0);
                g0 = __uint_as_float(ah[3] << 16); g1 = __uint_as_float(ah[3] & 0xffff0000u);
                al[3] = cvt_hl(e13 - g1, e12 - g0);
            }

            const uint* bh = bhs + ks * 8 + l;
            const uint* bl_ = bls + ks * 8 + l;
            #pragma unroll
            for (int nb = 0; nb < 8; nb++) {
                int ro = (nb * 8 + gid) * 68;
                uint b0h = bh[ro], b1h = bh[ro + 4];
                uint b0l = bl_[ro], b1l = bl_[ro + 4];
                mma16816(acc[nb], ah, b0h, b1h);
                mma16816(acc[nb], ah, b0l, b1l);
                mma16816(acc[nb], al, b0h, b1h);
            }
        }
        __syncthreads();
    }

    // rowsum reduce across the 4 lanes of each quad (deterministic)
    s0 += __shfl_xor_sync(0xffffffffu, s0, 1);
    s0 += __shfl_xor_sync(0xffffffffu, s0, 2);
    s1 += __shfl_xor_sync(0xffffffffu, s1, 1);
    s1 += __shfl_xor_sync(0xffffffffu, s1, 2);
    const float inv0 = 1.f / s0, inv1 = 1.f / s1;

    // epilogue: normalize + float2 scatter to (B,C,T,H,W)
    const int nrow0 = n0 + rb + gid, nrow1 = nrow0 + 8;
    const int ti0 = nrow0 >> 8, hi0 = (nrow0 >> 4) & 15, wi0 = nrow0 & 15;
    const int ti1 = nrow1 >> 8, hi1 = (nrow1 >> 4) & 15, wi1 = nrow1 & 15;
    #pragma unroll
    for (int nb = 0; nb < 8; nb++) {
        const int dp = nb * 8 + 2 * l;
        const int d = dp >> 4, p = dp & 15, sh = p >> 2, sw = p & 3;
        const int cch = (b * 128 + g * 4 + d);
        size_t o0 = ((size_t)(cch * 4 + ti0) * 64 + hi0 * 4 + sh) * 64 + wi0 * 4 + sw;
        size_t o1 = ((size_t)(cch * 4 + ti1) * 64 + hi1 * 4 + sh) * 64 + wi1 * 4 + sw;
        float2 v0 = make_float2(acc[nb][0] * inv0, acc[nb][1] * inv0);
        float2 v1 = make_float2(acc[nb][2] * inv1, acc[nb][3] * inv1);
        *(float2*)&out[o0] = v0;
        *(float2*)&out[o1] = v1;
    }
}

// ============================ launcher =======================================
extern "C" void kernel_launch(void* const* d_in, const int* in_sizes, int n_in,
                              void* d_out, int out_size)
{
    const float* x   = (const float*)d_in[0];
    const float* Wq  = (const float*)d_in[1];
    const float* Wk  = (const float*)d_in[2];
    const float* Wv  = (const float*)d_in[3];
    const float* gqg = (const float*)d_in[4];
    const float* gqb = (const float*)d_in[5];
    const float* gkg = (const float*)d_in[6];
    const float* gkb = (const float*)d_in[7];
    const float* gvg = (const float*)d_in[8];
    const float* gvb = (const float*)d_in[9];
    const float* rel_table = (const float*)d_in[10];
    const int*   rel_index = (const int*)d_in[11];
    float* out = (float*)d_out;

    cudaFuncSetAttribute(attn_kernel, cudaFuncAttributeMaxDynamicSharedMemorySize, ATT_SMEM);

    proj_kernel<<<dim3(256, B_, 3), 256>>>(x, Wq, Wk, Wv);
    stats_kernel<<<dim3(NH_, B_, 3), 256>>>();
    patch_kernel<<<16384, 256>>>(gqg, gqb, gkg, gkb, gvg, gvb);
    vtrans_kernel<<<dim3(8, 64), 256>>>();
    tblprep_kernel<<<NH_, 256>>>(rel_table);
    attn_kernel<<<dim3(8, NH_, B_), 256, ATT_SMEM>>>(rel_index, out);
}

// round 9
// speedup vs baseline: 4.3883x; 1.0398x over previous
#include <cuda_runtime.h>
#include <cuda_bf16.h>
#include <cuda_fp16.h>
#include <math.h>
#include <cstdint>

// ---------------- problem constants ----------------
#define B_    2
#define C_    128
#define NH_   32
#define DH_   4
#define SPAT  16384
#define NTOK  1024
#define TBL_  6727

typedef unsigned long long ull;
typedef unsigned int uint;

// ---------------- packed fp32x2 helpers ----------------
__device__ __forceinline__ ull pack2(float a) {
    ull r; uint ai = __float_as_uint(a);
    asm("mov.b64 %0, {%1, %1};" : "=l"(r) : "r"(ai));
    return r;
}
__device__ __forceinline__ ull packf2(float lo, float hi) {
    ull r;
    asm("mov.b64 %0, {%1, %2};" : "=l"(r) : "f"(lo), "f"(hi));
    return r;
}
__device__ __forceinline__ void ffma2(ull& d, ull a, ull b) {
    asm("fma.rn.f32x2 %0, %1, %2, %0;" : "+l"(d) : "l"(a), "l"(b));
}
__device__ __forceinline__ float2 unpack2(ull v) {
    float2 f; uint lo, hi;
    asm("mov.b64 {%0, %1}, %2;" : "=r"(lo), "=r"(hi) : "l"(v));
    f.x = __uint_as_float(lo); f.y = __uint_as_float(hi);
    return f;
}
__device__ __forceinline__ float ex2f(float x) {
    float r; asm("ex2.approx.f32 %0, %1;" : "=f"(r) : "f"(x)); return r;
}
// fp16x2 pack: lo -> low half, hi -> high half
__device__ __forceinline__ uint cvt_f16x2(float lo, float hi) {
    uint d;
    asm("cvt.rn.f16x2.f32 %0, %1, %2;" : "=r"(d) : "f"(hi), "f"(lo));
    return d;
}
// mma.sync m16n8k16 row.col f32.f16.f16.f32 (sm_80+; no 'a'-gated features)
__device__ __forceinline__ void mma16816h(float* c, const uint* a, uint b0, uint b1) {
    asm volatile(
        "mma.sync.aligned.m16n8k16.row.col.f32.f16.f16.f32 "
        "{%0,%1,%2,%3}, {%4,%5,%6,%7}, {%8,%9}, {%0,%1,%2,%3};"
        : "+f"(c[0]), "+f"(c[1]), "+f"(c[2]), "+f"(c[3])
        : "r"(a[0]), "r"(a[1]), "r"(a[2]), "r"(a[3]), "r"(b0), "r"(b1));
}

// ---------------- scratch ----------------
__device__ float g_y[3][B_][C_][SPAT];
__device__ float g_part[3][B_][NH_][256][2];
__device__ float g_stats[3][B_][NH_][2];
__device__ float g_qp[B_][NH_][NTOK][DH_];
__device__ float g_kp[B_][NH_][NTOK][DH_];
__device__ float g_vp[B_][NH_][NTOK][64];       // fp32 [n][dp]
__device__ uint  g_vh[B_ * NH_][64][512];       // fp16x2 V, [dp][m-pair]
__device__ float g_tbl2[NH_][TBL_];             // rel_table * log2(e)

// ================= K1: projections + GN partial stats ========================
__global__ __launch_bounds__(256) void proj_kernel(
    const float* __restrict__ x, const float* __restrict__ Wq,
    const float* __restrict__ Wk, const float* __restrict__ Wv)
{
    __shared__ float Wt[128][132];
    __shared__ float Xs[16][68];

    const int stile = blockIdx.x, b = blockIdx.y, proj = blockIdx.z;
    const float* W = (proj == 0) ? Wq : (proj == 1 ? Wk : Wv);
    const int tid = threadIdx.x;
    const int tx = tid & 15, ty = tid >> 4;

    for (int i = tid; i < 128 * 128; i += 256) {
        int o = i >> 7, c = i & 127;
        Wt[c][o] = W[i];
    }
    const int s0 = stile * 64;
    const float* xb = x + (size_t)b * C_ * SPAT;

    ull accL[8], accH[8];
    #pragma unroll
    for (int i = 0; i < 8; i++) { accL[i] = 0ull; accH[i] = 0ull; }

    for (int c0 = 0; c0 < 128; c0 += 16) {
        __syncthreads();
        for (int i = tid; i < 16 * 64; i += 256) {
            int cc = i >> 6, ss = i & 63;
            Xs[cc][ss] = xb[(size_t)(c0 + cc) * SPAT + s0 + ss];
        }
        __syncthreads();
        #pragma unroll
        for (int cc = 0; cc < 16; cc++) {
            float4 xv = *(const float4*)&Xs[cc][tx * 4];
            ull xL = ((const ull*)&xv)[0];
            ull xH = ((const ull*)&xv)[1];
            float4 wa = *(const float4*)&Wt[c0 + cc][ty * 8];
            float4 wb = *(const float4*)&Wt[c0 + cc][ty * 8 + 4];
            ull p0 = pack2(wa.x), p1 = pack2(wa.y), p2 = pack2(wa.z), p3 = pack2(wa.w);
            ull p4 = pack2(wb.x), p5 = pack2(wb.y), p6 = pack2(wb.z), p7 = pack2(wb.w);
            ffma2(accL[0], p0, xL); ffma2(accH[0], p0, xH);
            ffma2(accL[1], p1, xL); ffma2(accH[1], p1, xH);
            ffma2(accL[2], p2, xL); ffma2(accH[2], p2, xH);
            ffma2(accL[3], p3, xL); ffma2(accH[3], p3, xH);
            ffma2(accL[4], p4, xL); ffma2(accH[4], p4, xH);
            ffma2(accL[5], p5, xL); ffma2(accH[5], p5, xH);
            ffma2(accL[6], p6, xL); ffma2(accH[6], p6, xH);
            ffma2(accL[7], p7, xL); ffma2(accH[7], p7, xH);
        }
    }

    float* y = &g_y[proj][b][0][0];
    float gs[2] = {0.f, 0.f}, gq2[2] = {0.f, 0.f};
    #pragma unroll
    for (int i = 0; i < 8; i++) {
        int o = ty * 8 + i;
        float2 lo = unpack2(accL[i]);
        float2 hi = unpack2(accH[i]);
        float4 v = make_float4(lo.x, lo.y, hi.x, hi.y);
        *(float4*)&y[(size_t)o * SPAT + s0 + tx * 4] = v;
        int gi = i >> 2;
        gs[gi]  += v.x + v.y + v.z + v.w;
        gq2[gi] += v.x * v.x + v.y * v.y + v.z * v.z + v.w * v.w;
    }
    #pragma unroll
    for (int off = 8; off; off >>= 1) {
        gs[0]  += __shfl_down_sync(0xffffffffu, gs[0],  off);
        gs[1]  += __shfl_down_sync(0xffffffffu, gs[1],  off);
        gq2[0] += __shfl_down_sync(0xffffffffu, gq2[0], off);
        gq2[1] += __shfl_down_sync(0xffffffffu, gq2[1], off);
    }
    if (tx == 0) {
        int g0 = ty * 2;
        g_part[proj][b][g0    ][stile][0] = gs[0];
        g_part[proj][b][g0    ][stile][1] = gq2[0];
        g_part[proj][b][g0 + 1][stile][0] = gs[1];
        g_part[proj][b][g0 + 1][stile][1] = gq2[1];
    }
}

// ================= K2: finalize GN stats =====================================
__global__ __launch_bounds__(256) void stats_kernel()
{
    const int g = blockIdx.x, b = blockIdx.y, proj = blockIdx.z;
    const int tid = threadIdx.x;
    float s = g_part[proj][b][g][tid][0];
    float q = g_part[proj][b][g][tid][1];
    __shared__ float ss[8], sq[8];
    #pragma unroll
    for (int off = 16; off; off >>= 1) {
        s += __shfl_down_sync(0xffffffffu, s, off);
        q += __shfl_down_sync(0xffffffffu, q, off);
    }
    if ((tid & 31) == 0) { ss[tid >> 5] = s; sq[tid >> 5] = q; }
    __syncthreads();
    if (tid == 0) {
        float S = 0.f, Q = 0.f;
        #pragma unroll
        for (int i = 0; i < 8; i++) { S += ss[i]; Q += sq[i]; }
        const float inv = 1.f / 65536.f;
        float mu  = S * inv;
        float var = Q * inv - mu * mu;
        g_stats[proj][b][g][0] = mu;
        g_stats[proj][b][g][1] = rsqrtf(var + 1e-5f);
    }
}

// ================= K3: normalize + patchify + pool ===========================
__global__ __launch_bounds__(256) void patch_kernel(
    const float* __restrict__ gqg, const float* __restrict__ gqb,
    const float* __restrict__ gkg, const float* __restrict__ gkb,
    const float* __restrict__ gvg, const float* __restrict__ gvb)
{
    const int tid  = threadIdx.x;
    const int unit = blockIdx.x * 4 + (tid >> 6);
    const int n = unit & 1023;
    const int g = (unit >> 10) & 31;
    const int b = unit >> 15;
    const int local = tid & 63;
    const int d = local >> 4, p = local & 15;
    const int c = g * 4 + d;
    const int ti = n >> 8, hi = (n >> 4) & 15, wi = n & 15;
    const int sh = p >> 2, sw = p & 3;
    const int s = ti * 4096 + (hi * 4 + sh) * 64 + wi * 4 + sw;

    const float yq = g_y[0][b][c][s];
    const float yk = g_y[1][b][c][s];
    const float yv = g_y[2][b][c][s];

    float nq = (yq - g_stats[0][b][g][0]) * g_stats[0][b][g][1] * gqg[c] + gqb[c];
    float nk = (yk - g_stats[1][b][g][0]) * g_stats[1][b][g][1] * gkg[c] + gkb[c];
    float nv = (yv - g_stats[2][b][g][0]) * g_stats[2][b][g][1] * gvg[c] + gvb[c];

    g_vp[b][g][n][d * 16 + p] = nv;

    #pragma unroll
    for (int off = 8; off; off >>= 1) {
        nq += __shfl_down_sync(0xffffffffu, nq, off);
        nk += __shfl_down_sync(0xffffffffu, nk, off);
    }
    if (p == 0) {
        g_qp[b][g][n][d] = nq * (1.f / 16.f);
        g_kp[b][g][n][d] = nk * (1.f / 16.f);
    }
}

// ================= K3b: vp -> transposed fp16 [dp][m-pair] ===================
__global__ __launch_bounds__(256) void vtrans_kernel()
{
    __shared__ float ts[128][65];
    const int n0 = blockIdx.x * 128, bg = blockIdx.y;
    const int tid = threadIdx.x;
    const float* vp = &g_vp[0][0][0][0] + (size_t)bg * NTOK * 64;

    for (int i = tid; i < 128 * 64; i += 256) {
        int n = i >> 6, dp = i & 63;
        ts[n][dp] = vp[(size_t)(n0 + n) * 64 + dp];
    }
    __syncthreads();
    for (int i = tid; i < 64 * 64; i += 256) {
        int dp = i >> 6, j = i & 63;
        float v0 = ts[2 * j][dp], v1 = ts[2 * j + 1][dp];
        g_vh[bg][dp][(n0 >> 1) + j] = cvt_f16x2(v0, v1);  // v0 low, v1 high
    }
}

// ================= K3c: prescale bias table by log2(e) =======================
__global__ __launch_bounds__(256) void tblprep_kernel(const float* __restrict__ rel_table)
{
    const int g = blockIdx.x;
    for (int i = threadIdx.x; i < TBL_; i += 256)
        g_tbl2[g][i] = rel_table[g * TBL_ + i] * 1.4426950408889634f;
}

// ================= K4: attention via mma.sync fp16 (single pass) =============
// grid (8 mtiles, 32 g, 2 b), block 256 (8 warps). 128 rows/CTA, 16 rows/warp.
// smem: kp 16KB | q 2KB | Vh 17408B = 35840B -> 3 CTAs/SM
#define ATT_SMEM 35840

__global__ __launch_bounds__(256, 3) void attn_kernel(
    const int* __restrict__ rel_index,
    float*     __restrict__ out)
{
    extern __shared__ float smem[];
    float4* kp_s = (float4*)smem;               // 1024 float4
    float4* q_s  = (float4*)(smem + 4096);      // 128 float4 (prescaled)
    uint*   vhs  = (uint*)(smem + 4608);        // 64 rows x 68 u32 (stride pad)

    const int mtile = blockIdx.x, g = blockIdx.y, b = blockIdx.z;
    const int n0 = mtile * 128;
    const int bg = b * 32 + g;
    const int tid = threadIdx.x, wid = tid >> 5, lane = tid & 31;
    const int l = lane & 3, gid = lane >> 2;

    {
        const float4* kp = (const float4*)&g_kp[b][g][0][0];
        for (int i = tid; i < 1024; i += 256) kp_s[i] = kp[i];
        const float4* qp = (const float4*)&g_qp[b][g][0][0];
        const float QS = 0.72134752044448170f;   // 0.5 * log2(e)
        for (int i = tid; i < 128; i += 256) {
            float4 q = qp[n0 + i];
            q.x *= QS; q.y *= QS; q.z *= QS; q.w *= QS;
            q_s[i] = q;
        }
    }
    __syncthreads();

    // hoisted per-warp row data
    const int rb = wid * 16;
    float4 q0 = q_s[rb + gid], q1 = q_s[rb + gid + 8];
    ull q0x = pack2(q0.x), q0y = pack2(q0.y), q0z = pack2(q0.z), q0w = pack2(q0.w);
    ull q1x = pack2(q1.x), q1y = pack2(q1.y), q1z = pack2(q1.z), q1w = pack2(q1.w);
    const float* tbl = &g_tbl2[g][0];
    const int* ridx0 = rel_index + (size_t)(n0 + rb + gid) * 1024;
    const int* ridx1 = ridx0 + 8 * 1024;

    float acc[8][4];
    #pragma unroll
    for (int i = 0; i < 8; i++)
        #pragma unroll
        for (int j = 0; j < 4; j++) acc[i][j] = 0.f;
    float s0 = 0.f, s1 = 0.f;

    for (int c = 0; c < 8; c++) {
        // stage V chunk (128 m = 64 pairs per dp row), fp16
        __syncthreads();
        for (int i = tid; i < 1024; i += 256) {
            int dp = i >> 4, j4 = i & 15;
            float4 vh = *(const float4*)&g_vh[bg][dp][c * 64 + j4 * 4];
            *(float4*)&vhs[dp * 68 + j4 * 4] = vh;
        }
        __syncthreads();

        #pragma unroll
        for (int ks = 0; ks < 8; ks++) {
            const int m00 = c * 128 + ks * 16 + 2 * l;
            float4 kv00 = kp_s[m00],     kv01 = kp_s[m00 + 1];
            float4 kv10 = kp_s[m00 + 8], kv11 = kp_s[m00 + 9];

            int2 iA = __ldg((const int2*)(ridx0 + m00));
            int2 iB = __ldg((const int2*)(ridx0 + m00 + 8));
            int2 iC = __ldg((const int2*)(ridx1 + m00));
            int2 iD = __ldg((const int2*)(ridx1 + m00 + 8));
            ull d0a = packf2(__ldg(tbl + iA.x), __ldg(tbl + iA.y));
            ull d0b = packf2(__ldg(tbl + iB.x), __ldg(tbl + iB.y));
            ull d1a = packf2(__ldg(tbl + iC.x), __ldg(tbl + iC.y));
            ull d1b = packf2(__ldg(tbl + iD.x), __ldg(tbl + iD.y));

            ull kax = packf2(kv00.x, kv01.x), kay = packf2(kv00.y, kv01.y);
            ull kaz = packf2(kv00.z, kv01.z), kaw = packf2(kv00.w, kv01.w);
            ull kbx = packf2(kv10.x, kv11.x), kby = packf2(kv10.y, kv11.y);
            ull kbz = packf2(kv10.z, kv11.z), kbw = packf2(kv10.w, kv11.w);

            ffma2(d0a, q0x, kax); ffma2(d0a, q0y, kay); ffma2(d0a, q0z, kaz); ffma2(d0a, q0w, kaw);
            ffma2(d0b, q0x, kbx); ffma2(d0b, q0y, kby); ffma2(d0b, q0z, kbz); ffma2(d0b, q0w, kbw);
            ffma2(d1a, q1x, kax); ffma2(d1a, q1y, kay); ffma2(d1a, q1z, kaz); ffma2(d1a, q1w, kaw);
            ffma2(d1b, q1x, kbx); ffma2(d1b, q1y, kby); ffma2(d1b, q1z, kbz); ffma2(d1b, q1w, kbw);

            float2 f0a = unpack2(d0a), f0b = unpack2(d0b);
            float2 f1a = unpack2(d1a), f1b = unpack2(d1b);
            float e00 = ex2f(f0a.x), e01 = ex2f(f0a.y), e02 = ex2f(f0b.x), e03 = ex2f(f0b.y);
            float e10 = ex2f(f1a.x), e11 = ex2f(f1a.y), e12 = ex2f(f1b.x), e13 = ex2f(f1b.y);
            s0 += (e00 + e01) + (e02 + e03);
            s1 += (e10 + e11) + (e12 + e13);

            uint ah[4];
            ah[0] = cvt_f16x2(e00, e01);
            ah[1] = cvt_f16x2(e10, e11);
            ah[2] = cvt_f16x2(e02, e03);
            ah[3] = cvt_f16x2(e12, e13);

            const uint* bh = vhs + ks * 8 + l;
            #pragma unroll
            for (int nb = 0; nb < 8; nb++) {
                int ro = (nb * 8 + gid) * 68;
                uint b0 = bh[ro], b1 = bh[ro + 4];
                mma16816h(acc[nb], ah, b0, b1);
            }
        }
    }

    // rowsum reduce across the 4 lanes of each quad (deterministic)
    s0 += __shfl_xor_sync(0xffffffffu, s0, 1);
    s0 += __shfl_xor_sync(0xffffffffu, s0, 2);
    s1 += __shfl_xor_sync(0xffffffffu, s1, 1);
    s1 += __shfl_xor_sync(0xffffffffu, s1, 2);
    const float inv0 = 1.f / s0, inv1 = 1.f / s1;

    // epilogue: normalize + float2 scatter to (B,C,T,H,W)
    const int nrow0 = n0 + rb + gid, nrow1 = nrow0 + 8;
    const int ti0 = nrow0 >> 8, hi0 = (nrow0 >> 4) & 15, wi0 = nrow0 & 15;
    const int ti1 = nrow1 >> 8, hi1 = (nrow1 >> 4) & 15, wi1 = nrow1 & 15;
    #pragma unroll
    for (int nb = 0; nb < 8; nb++) {
        const int dp = nb * 8 + 2 * l;
        const int d = dp >> 4, p = dp & 15, sh = p >> 2, sw = p & 3;
        const int cch = (b * 128 + g * 4 + d);
        size_t o0 = ((size_t)(cch * 4 + ti0) * 64 + hi0 * 4 + sh) * 64 + wi0 * 4 + sw;
        size_t o1 = ((size_t)(cch * 4 + ti1) * 64 + hi1 * 4 + sh) * 64 + wi1 * 4 + sw;
        float2 v0 = make_float2(acc[nb][0] * inv0, acc[nb][1] * inv0);
        float2 v1 = make_float2(acc[nb][2] * inv1, acc[nb][3] * inv1);
        *(float2*)&out[o0] = v0;
        *(float2*)&out[o1] = v1;
    }
}

// ============================ launcher =======================================
extern "C" void kernel_launch(void* const* d_in, const int* in_sizes, int n_in,
                              void* d_out, int out_size)
{
    const float* x   = (const float*)d_in[0];
    const float* Wq  = (const float*)d_in[1];
    const float* Wk  = (const float*)d_in[2];
    const float* Wv  = (const float*)d_in[3];
    const float* gqg = (const float*)d_in[4];
    const float* gqb = (const float*)d_in[5];
    const float* gkg = (const float*)d_in[6];
    const float* gkb = (const float*)d_in[7];
    const float* gvg = (const float*)d_in[8];
    const float* gvb = (const float*)d_in[9];
    const float* rel_table = (const float*)d_in[10];
    const int*   rel_index = (const int*)d_in[11];
    float* out = (float*)d_out;

    cudaFuncSetAttribute(attn_kernel, cudaFuncAttributeMaxDynamicSharedMemorySize, ATT_SMEM);

    proj_kernel<<<dim3(256, B_, 3), 256>>>(x, Wq, Wk, Wv);
    stats_kernel<<<dim3(NH_, B_, 3), 256>>>();
    patch_kernel<<<16384, 256>>>(gqg, gqb, gkg, gkb, gvg, gvb);
    vtrans_kernel<<<dim3(8, 64), 256>>>();
    tblprep_kernel<<<NH_, 256>>>(rel_table);
    attn_kernel<<<dim3(8, NH_, B_), 256, ATT_SMEM>>>(rel_index, out);
}

// round 12
// speedup vs baseline: 5.3196x; 1.2122x over previous
#include <cuda_runtime.h>
#include <cuda_bf16.h>
#include <cuda_fp16.h>
#include <math.h>
#include <cstdint>

// ---------------- problem constants ----------------
#define B_    2
#define C_    128
#define NH_   32
#define DH_   4
#define SPAT  16384
#define NTOK  1024
#define TBL_  6727

typedef unsigned long long ull;
typedef unsigned int uint;

// ---------------- packed fp32x2 helpers ----------------
__device__ __forceinline__ ull pack2(float a) {
    ull r; uint ai = __float_as_uint(a);
    asm("mov.b64 %0, {%1, %1};" : "=l"(r) : "r"(ai));
    return r;
}
__device__ __forceinline__ ull packf2(float lo, float hi) {
    ull r;
    asm("mov.b64 %0, {%1, %2};" : "=l"(r) : "f"(lo), "f"(hi));
    return r;
}
__device__ __forceinline__ void ffma2(ull& d, ull a, ull b) {
    asm("fma.rn.f32x2 %0, %1, %2, %0;" : "+l"(d) : "l"(a), "l"(b));
}
__device__ __forceinline__ float2 unpack2(ull v) {
    float2 f; uint lo, hi;
    asm("mov.b64 {%0, %1}, %2;" : "=r"(lo), "=r"(hi) : "l"(v));
    f.x = __uint_as_float(lo); f.y = __uint_as_float(hi);
    return f;
}
__device__ __forceinline__ float ex2f(float x) {
    float r; asm("ex2.approx.f32 %0, %1;" : "=f"(r) : "f"(x)); return r;
}
// fp16x2 pack: first arg -> low half, second -> high half
__device__ __forceinline__ uint cvt_f16x2(float lo, float hi) {
    uint d;
    asm("cvt.rn.f16x2.f32 %0, %1, %2;" : "=r"(d) : "f"(hi), "f"(lo));
    return d;
}
// mma.sync m16n8k16 row.col f32.f16.f16.f32
__device__ __forceinline__ void mma16816h(float* c, const uint* a, uint b0, uint b1) {
    asm volatile(
        "mma.sync.aligned.m16n8k16.row.col.f32.f16.f16.f32 "
        "{%0,%1,%2,%3}, {%4,%5,%6,%7}, {%8,%9}, {%0,%1,%2,%3};"
        : "+f"(c[0]), "+f"(c[1]), "+f"(c[2]), "+f"(c[3])
        : "r"(a[0]), "r"(a[1]), "r"(a[2]), "r"(a[3]), "r"(b0), "r"(b1));
}

// ---------------- scratch ----------------
__device__ float g_y[3][B_][C_][SPAT];
__device__ float g_part[3][B_][NH_][256][2];
__device__ float g_stats[3][B_][NH_][2];
__device__ float g_qp[B_][NH_][NTOK][DH_];
__device__ float g_kp[B_][NH_][NTOK][DH_];
__device__ float g_vp[B_][NH_][NTOK][64];       // fp32 [n][dp]
__device__ uint  g_vh[B_ * NH_][64][512];       // fp16x2 V, [dp][m-pair]
__device__ float g_tbl2[NH_][TBL_];             // rel_table * log2(e)
__device__ uint  g_wh2[3][128 * 64];            // W hi fp16x2 [o][c-pair]
__device__ uint  g_wl2[3][128 * 64];            // W lo fp16x2
__device__ unsigned short g_idx16[NTOK * NTOK]; // rel_index as u16

// ================= K0a: split W into fp16 hi/lo pairs ========================
__global__ __launch_bounds__(256) void wprep_kernel(
    const float* __restrict__ Wq, const float* __restrict__ Wk,
    const float* __restrict__ Wv)
{
    const int proj = blockIdx.x;
    const float* W = (proj == 0) ? Wq : (proj == 1 ? Wk : Wv);
    for (int i = threadIdx.x; i < 128 * 64; i += 256) {
        int o = i >> 6, cp = i & 63;
        float v0 = W[o * 128 + 2 * cp], v1 = W[o * 128 + 2 * cp + 1];
        uint h2 = cvt_f16x2(v0, v1);
        __half2 hh = *(__half2*)&h2;
        uint l2 = cvt_f16x2(v0 - __low2float(hh), v1 - __high2float(hh));
        g_wh2[proj][i] = h2;
        g_wl2[proj][i] = l2;
    }
}

// ================= K0b: rel_index -> u16 =====================================
__global__ __launch_bounds__(256) void iprep_kernel(const int* __restrict__ rel_index)
{
    const int i = blockIdx.x * 256 + threadIdx.x;   // 262144 int4 groups
    int4 v = ((const int4*)rel_index)[i];
    ushort4 u;
    u.x = (unsigned short)v.x; u.y = (unsigned short)v.y;
    u.z = (unsigned short)v.z; u.w = (unsigned short)v.w;
    ((ushort4*)g_idx16)[i] = u;
}

// ================= K0c: prescale bias table by log2(e) =======================
__global__ __launch_bounds__(256) void tblprep_kernel(const float* __restrict__ rel_table)
{
    const int g = blockIdx.x;
    for (int i = threadIdx.x; i < TBL_; i += 256)
        g_tbl2[g][i] = rel_table[g * TBL_ + i] * 1.4426950408889634f;
}

// ================= K1: projections via mma.sync fp16 3-pass + GN partials ====
// grid (256 stiles, B, 3 proj), block 256 (8 warps). Tile 128o x 64s, K=128.
__global__ __launch_bounds__(256) void proj_kernel(const float* __restrict__ x)
{
    __shared__ uint Xh[64 * 68];      // [s][c-pair] fp16x2 hi, stride 68 pad
    __shared__ uint Xl[64 * 68];      // lo
    __shared__ float rsum[128], rsq[128];

    const int stile = blockIdx.x, b = blockIdx.y, proj = blockIdx.z;
    const int s0 = stile * 64;
    const int tid = threadIdx.x, wid = tid >> 5, lane = tid & 31;
    const int l = lane & 3, gid = lane >> 2;
    const float* xb = x + (size_t)b * C_ * SPAT;

    // ---- produce X split tiles (transpose c-major -> [s][cp]) ----
    {
        const int s = tid & 63, cpb = tid >> 6;
        #pragma unroll 4
        for (int it = 0; it < 16; it++) {
            int cp = cpb * 16 + it;
            float v0 = xb[(size_t)(2 * cp) * SPAT + s0 + s];
            float v1 = xb[(size_t)(2 * cp + 1) * SPAT + s0 + s];
            uint h2 = cvt_f16x2(v0, v1);
            __half2 hh = *(__half2*)&h2;
            uint l2 = cvt_f16x2(v0 - __low2float(hh), v1 - __high2float(hh));
            Xh[s * 68 + cp] = h2;
            Xl[s * 68 + cp] = l2;
        }
    }
    __syncthreads();

    // ---- mainloop: warp w -> o-rows [w*16, w*16+16), all 64 s ----
    const uint* wh = &g_wh2[proj][0];
    const uint* wl = &g_wl2[proj][0];
    const int ob = wid * 16;
    const int row0 = ob + gid, row1 = row0 + 8;

    float acc[8][4];
    #pragma unroll
    for (int i = 0; i < 8; i++)
        #pragma unroll
        for (int j = 0; j < 4; j++) acc[i][j] = 0.f;

    #pragma unroll
    for (int ks = 0; ks < 8; ks++) {
        const int cp0 = ks * 8 + l, cp1 = cp0 + 4;
        uint ahi[4], alo[4];
        ahi[0] = __ldg(wh + row0 * 64 + cp0);
        ahi[1] = __ldg(wh + row1 * 64 + cp0);
        ahi[2] = __ldg(wh + row0 * 64 + cp1);
        ahi[3] = __ldg(wh + row1 * 64 + cp1);
        alo[0] = __ldg(wl + row0 * 64 + cp0);
        alo[1] = __ldg(wl + row1 * 64 + cp0);
        alo[2] = __ldg(wl + row0 * 64 + cp1);
        alo[3] = __ldg(wl + row1 * 64 + cp1);
        #pragma unroll
        for (int nt = 0; nt < 8; nt++) {
            const uint* bp = Xh + (nt * 8 + gid) * 68 + cp0;
            const uint* bq = Xl + (nt * 8 + gid) * 68 + cp0;
            uint b0h = bp[0], b1h = bp[4];
            uint b0l = bq[0], b1l = bq[4];
            mma16816h(acc[nt], ahi, b0h, b1h);
            mma16816h(acc[nt], ahi, b0l, b1l);
            mma16816h(acc[nt], alo, b0h, b1h);
        }
    }

    // ---- epilogue: store y + per-row partial stats ----
    float* y = &g_y[proj][b][0][0];
    float s_r0 = 0.f, q_r0 = 0.f, s_r1 = 0.f, q_r1 = 0.f;
    #pragma unroll
    for (int nt = 0; nt < 8; nt++) {
        float c0 = acc[nt][0], c1 = acc[nt][1], c2 = acc[nt][2], c3 = acc[nt][3];
        int col = s0 + nt * 8 + 2 * l;
        *(float2*)&y[(size_t)row0 * SPAT + col] = make_float2(c0, c1);
        *(float2*)&y[(size_t)row1 * SPAT + col] = make_float2(c2, c3);
        s_r0 += c0 + c1; q_r0 += c0 * c0 + c1 * c1;
        s_r1 += c2 + c3; q_r1 += c2 * c2 + c3 * c3;
    }
    // quad reduce (lanes gid*4 + l, l = 0..3)
    s_r0 += __shfl_down_sync(0xffffffffu, s_r0, 1);
    s_r0 += __shfl_down_sync(0xffffffffu, s_r0, 2);
    q_r0 += __shfl_down_sync(0xffffffffu, q_r0, 1);
    q_r0 += __shfl_down_sync(0xffffffffu, q_r0, 2);
    s_r1 += __shfl_down_sync(0xffffffffu, s_r1, 1);
    s_r1 += __shfl_down_sync(0xffffffffu, s_r1, 2);
    q_r1 += __shfl_down_sync(0xffffffffu, q_r1, 1);
    q_r1 += __shfl_down_sync(0xffffffffu, q_r1, 2);
    if (l == 0) {
        rsum[row0] = s_r0; rsq[row0] = q_r0;
        rsum[row1] = s_r1; rsq[row1] = q_r1;
    }
    __syncthreads();
    if (tid < 32) {
        float S = rsum[tid * 4] + rsum[tid * 4 + 1] + rsum[tid * 4 + 2] + rsum[tid * 4 + 3];
        float Q = rsq[tid * 4] + rsq[tid * 4 + 1] + rsq[tid * 4 + 2] + rsq[tid * 4 + 3];
        g_part[proj][b][tid][stile][0] = S;
        g_part[proj][b][tid][stile][1] = Q;
    }
}

// ================= K2: finalize GN stats =====================================
__global__ __launch_bounds__(256) void stats_kernel()
{
    const int g = blockIdx.x, b = blockIdx.y, proj = blockIdx.z;
    const int tid = threadIdx.x;
    float s = g_part[proj][b][g][tid][0];
    float q = g_part[proj][b][g][tid][1];
    __shared__ float ss[8], sq[8];
    #pragma unroll
    for (int off = 16; off; off >>= 1) {
        s += __shfl_down_sync(0xffffffffu, s, off);
        q += __shfl_down_sync(0xffffffffu, q, off);
    }
    if ((tid & 31) == 0) { ss[tid >> 5] = s; sq[tid >> 5] = q; }
    __syncthreads();
    if (tid == 0) {
        float S = 0.f, Q = 0.f;
        #pragma unroll
        for (int i = 0; i < 8; i++) { S += ss[i]; Q += sq[i]; }
        const float inv = 1.f / 65536.f;
        float mu  = S * inv;
        float var = Q * inv - mu * mu;
        g_stats[proj][b][g][0] = mu;
        g_stats[proj][b][g][1] = rsqrtf(var + 1e-5f);
    }
}

// ================= K3: normalize + patchify + pool ===========================
__global__ __launch_bounds__(256) void patch_kernel(
    const float* __restrict__ gqg, const float* __restrict__ gqb,
    const float* __restrict__ gkg, const float* __restrict__ gkb,
    const float* __restrict__ gvg, const float* __restrict__ gvb)
{
    const int tid  = threadIdx.x;
    const int unit = blockIdx.x * 4 + (tid >> 6);
    const int n = unit & 1023;
    const int g = (unit >> 10) & 31;
    const int b = unit >> 15;
    const int local = tid & 63;
    const int d = local >> 4, p = local & 15;
    const int c = g * 4 + d;
    const int ti = n >> 8, hi = (n >> 4) & 15, wi = n & 15;
    const int sh = p >> 2, sw = p & 3;
    const int s = ti * 4096 + (hi * 4 + sh) * 64 + wi * 4 + sw;

    const float yq = g_y[0][b][c][s];
    const float yk = g_y[1][b][c][s];
    const float yv = g_y[2][b][c][s];

    float nq = (yq - g_stats[0][b][g][0]) * g_stats[0][b][g][1] * gqg[c] + gqb[c];
    float nk = (yk - g_stats[1][b][g][0]) * g_stats[1][b][g][1] * gkg[c] + gkb[c];
    float nv = (yv - g_stats[2][b][g][0]) * g_stats[2][b][g][1] * gvg[c] + gvb[c];

    g_vp[b][g][n][d * 16 + p] = nv;

    #pragma unroll
    for (int off = 8; off; off >>= 1) {
        nq += __shfl_down_sync(0xffffffffu, nq, off);
        nk += __shfl_down_sync(0xffffffffu, nk, off);
    }
    if (p == 0) {
        g_qp[b][g][n][d] = nq * (1.f / 16.f);
        g_kp[b][g][n][d] = nk * (1.f / 16.f);
    }
}

// ================= K3b: vp -> transposed fp16 [dp][m-pair] ===================
__global__ __launch_bounds__(256) void vtrans_kernel()
{
    __shared__ float ts[128][65];
    const int n0 = blockIdx.x * 128, bg = blockIdx.y;
    const int tid = threadIdx.x;
    const float* vp = &g_vp[0][0][0][0] + (size_t)bg * NTOK * 64;

    for (int i = tid; i < 128 * 64; i += 256) {
        int n = i >> 6, dp = i & 63;
        ts[n][dp] = vp[(size_t)(n0 + n) * 64 + dp];
    }
    __syncthreads();
    for (int i = tid; i < 64 * 64; i += 256) {
        int dp = i >> 6, j = i & 63;
        float v0 = ts[2 * j][dp], v1 = ts[2 * j + 1][dp];
        g_vh[bg][dp][(n0 >> 1) + j] = cvt_f16x2(v0, v1);
    }
}

// ================= K4: attention via mma.sync fp16 (single pass) =============
// grid (8 mtiles, 32 g, 2 b), block 256 (8 warps). 128 rows/CTA, 16 rows/warp.
// smem: kp 16KB | q 2KB | Vh 17408B = 35840B -> 3 CTAs/SM
#define ATT_SMEM 35840

__global__ __launch_bounds__(256, 3) void attn_kernel(float* __restrict__ out)
{
    extern __shared__ float smem[];
    float4* kp_s = (float4*)smem;               // 1024 float4
    float4* q_s  = (float4*)(smem + 4096);      // 128 float4 (prescaled)
    uint*   vhs  = (uint*)(smem + 4608);        // 64 rows x 68 u32 (stride pad)

    const int mtile = blockIdx.x, g = blockIdx.y, b = blockIdx.z;
    const int n0 = mtile * 128;
    const int bg = b * 32 + g;
    const int tid = threadIdx.x, wid = tid >> 5, lane = tid & 31;
    const int l = lane & 3, gid = lane >> 2;

    {
        const float4* kp = (const float4*)&g_kp[b][g][0][0];
        for (int i = tid; i < 1024; i += 256) kp_s[i] = kp[i];
        const float4* qp = (const float4*)&g_qp[b][g][0][0];
        const float QS = 0.72134752044448170f;   // 0.5 * log2(e)
        for (int i = tid; i < 128; i += 256) {
            float4 q = qp[n0 + i];
            q.x *= QS; q.y *= QS; q.z *= QS; q.w *= QS;
            q_s[i] = q;
        }
    }
    __syncthreads();

    const int rb = wid * 16;
    float4 q0 = q_s[rb + gid], q1 = q_s[rb + gid + 8];
    ull q0x = pack2(q0.x), q0y = pack2(q0.y), q0z = pack2(q0.z), q0w = pack2(q0.w);
    ull q1x = pack2(q1.x), q1y = pack2(q1.y), q1z = pack2(q1.z), q1w = pack2(q1.w);
    const float* tbl = &g_tbl2[g][0];
    const unsigned short* r0p = g_idx16 + (size_t)(n0 + rb + gid) * 1024;
    const unsigned short* r1p = r0p + 8 * 1024;

    float acc[8][4];
    #pragma unroll
    for (int i = 0; i < 8; i++)
        #pragma unroll
        for (int j = 0; j < 4; j++) acc[i][j] = 0.f;
    float s0 = 0.f, s1 = 0.f;

    for (int c = 0; c < 8; c++) {
        __syncthreads();
        for (int i = tid; i < 1024; i += 256) {
            int dp = i >> 4, j4 = i & 15;
            float4 vh = *(const float4*)&g_vh[bg][dp][c * 64 + j4 * 4];
            *(float4*)&vhs[dp * 68 + j4 * 4] = vh;
        }
        __syncthreads();

        #pragma unroll
        for (int ks = 0; ks < 8; ks++) {
            const int m00 = c * 128 + ks * 16 + 2 * l;
            float4 kv00 = kp_s[m00],     kv01 = kp_s[m00 + 1];
            float4 kv10 = kp_s[m00 + 8], kv11 = kp_s[m00 + 9];

            ushort2 iA = *(const ushort2*)(r0p + m00);
            ushort2 iB = *(const ushort2*)(r0p + m00 + 8);
            ushort2 iC = *(const ushort2*)(r1p + m00);
            ushort2 iD = *(const ushort2*)(r1p + m00 + 8);
            ull d0a = packf2(__ldg(tbl + iA.x), __ldg(tbl + iA.y));
            ull d0b = packf2(__ldg(tbl + iB.x), __ldg(tbl + iB.y));
            ull d1a = packf2(__ldg(tbl + iC.x), __ldg(tbl + iC.y));
            ull d1b = packf2(__ldg(tbl + iD.x), __ldg(tbl + iD.y));

            ull kax = packf2(kv00.x, kv01.x), kay = packf2(kv00.y, kv01.y);
            ull kaz = packf2(kv00.z, kv01.z), kaw = packf2(kv00.w, kv01.w);
            ull kbx = packf2(kv10.x, kv11.x), kby = packf2(kv10.y, kv11.y);
            ull kbz = packf2(kv10.z, kv11.z), kbw = packf2(kv10.w, kv11.w);

            ffma2(d0a, q0x, kax); ffma2(d0a, q0y, kay); ffma2(d0a, q0z, kaz); ffma2(d0a, q0w, kaw);
            ffma2(d0b, q0x, kbx); ffma2(d0b, q0y, kby); ffma2(d0b, q0z, kbz); ffma2(d0b, q0w, kbw);
            ffma2(d1a, q1x, kax); ffma2(d1a, q1y, kay); ffma2(d1a, q1z, kaz); ffma2(d1a, q1w, kaw);
            ffma2(d1b, q1x, kbx); ffma2(d1b, q1y, kby); ffma2(d1b, q1z, kbz); ffma2(d1b, q1w, kbw);

            float2 f0a = unpack2(d0a), f0b = unpack2(d0b);
            float2 f1a = unpack2(d1a), f1b = unpack2(d1b);
            float e00 = ex2f(f0a.x), e01 = ex2f(f0a.y), e02 = ex2f(f0b.x), e03 = ex2f(f0b.y);
            float e10 = ex2f(f1a.x), e11 = ex2f(f1a.y), e12 = ex2f(f1b.x), e13 = ex2f(f1b.y);
            s0 += (e00 + e01) + (e02 + e03);
            s1 += (e10 + e11) + (e12 + e13);

            uint ah[4];
            ah[0] = cvt_f16x2(e00, e01);
            ah[1] = cvt_f16x2(e10, e11);
            ah[2] = cvt_f16x2(e02, e03);
            ah[3] = cvt_f16x2(e12, e13);

            const uint* bh = vhs + ks * 8 + l;
            #pragma unroll
            for (int nb = 0; nb < 8; nb++) {
                int ro = (nb * 8 + gid) * 68;
                mma16816h(acc[nb], ah, bh[ro], bh[ro + 4]);
            }
        }
    }

    s0 += __shfl_xor_sync(0xffffffffu, s0, 1);
    s0 += __shfl_xor_sync(0xffffffffu, s0, 2);
    s1 += __shfl_xor_sync(0xffffffffu, s1, 1);
    s1 += __shfl_xor_sync(0xffffffffu, s1, 2);
    const float inv0 = 1.f / s0, inv1 = 1.f / s1;

    const int nrow0 = n0 + rb + gid, nrow1 = nrow0 + 8;
    const int ti0 = nrow0 >> 8, hi0 = (nrow0 >> 4) & 15, wi0 = nrow0 & 15;
    const int ti1 = nrow1 >> 8, hi1 = (nrow1 >> 4) & 15, wi1 = nrow1 & 15;
    #pragma unroll
    for (int nb = 0; nb < 8; nb++) {
        const int dp = nb * 8 + 2 * l;
        const int d = dp >> 4, p = dp & 15, sh = p >> 2, sw = p & 3;
        const int cch = (b * 128 + g * 4 + d);
        size_t o0 = ((size_t)(cch * 4 + ti0) * 64 + hi0 * 4 + sh) * 64 + wi0 * 4 + sw;
        size_t o1 = ((size_t)(cch * 4 + ti1) * 64 + hi1 * 4 + sh) * 64 + wi1 * 4 + sw;
        float2 v0 = make_float2(acc[nb][0] * inv0, acc[nb][1] * inv0);
        float2 v1 = make_float2(acc[nb][2] * inv1, acc[nb][3] * inv1);
        *(float2*)&out[o0] = v0;
        *(float2*)&out[o1] = v1;
    }
}

// ============================ launcher =======================================
extern "C" void kernel_launch(void* const* d_in, const int* in_sizes, int n_in,
                              void* d_out, int out_size)
{
    const float* x   = (const float*)d_in[0];
    const float* Wq  = (const float*)d_in[1];
    const float* Wk  = (const float*)d_in[2];
    const float* Wv  = (const float*)d_in[3];
    const float* gqg = (const float*)d_in[4];
    const float* gqb = (const float*)d_in[5];
    const float* gkg = (const float*)d_in[6];
    const float* gkb = (const float*)d_in[7];
    const float* gvg = (const float*)d_in[8];
    const float* gvb = (const float*)d_in[9];
    const float* rel_table = (const float*)d_in[10];
    const int*   rel_index = (const int*)d_in[11];
    float* out = (float*)d_out;

    cudaFuncSetAttribute(attn_kernel, cudaFuncAttributeMaxDynamicSharedMemorySize, ATT_SMEM);

    wprep_kernel<<<3, 256>>>(Wq, Wk, Wv);
    iprep_kernel<<<1024, 256>>>(rel_index);
    tblprep_kernel<<<NH_, 256>>>(rel_table);
    proj_kernel<<<dim3(256, B_, 3), 256>>>(x);
    stats_kernel<<<dim3(NH_, B_, 3), 256>>>();
    patch_kernel<<<16384, 256>>>(gqg, gqb, gkg, gkb, gvg, gvb);
    vtrans_kernel<<<dim3(8, 64), 256>>>();
    attn_kernel<<<dim3(8, NH_, B_), 256, ATT_SMEM>>>(out);
}